// round 2
// baseline (speedup 1.0000x reference)
#include <cuda_runtime.h>
#include <cuda_bf16.h>
#include <math.h>

#define N_NODES 18432
#define HDIM    256
#define EDIM    64
#define FDIM    512
#define NLAY    2
#define E_BIG   294912
#define E_SML   65536
#define EB      4

// ---------------- scratch (device globals; no allocs allowed) ----------------
__device__ float g_xl [N_NODES*HDIM];
__device__ float g_xr [N_NODES*HDIM];
__device__ float g_q  [N_NODES*HDIM];
__device__ float g_k  [N_NODES*HDIM];
__device__ float g_v  [N_NODES*HDIM];
__device__ float g_msg[N_NODES*HDIM];
__device__ float g_den[N_NODES*8];
__device__ float g_aggl[N_NODES*HDIM];
__device__ float g_aggr[N_NODES*HDIM];
__device__ float g_hid[N_NODES*FDIM];

__device__ __forceinline__ float gelu_f(float x){
    return 0.5f*x*(1.0f + tanhf(0.7978845608028654f*(x + 0.044715f*x*x*x)));
}

// ------- fp32 SGEMM: 128x128 tile, 256 thr, 8x8/thread, BK=8, double-buffered
// QKV3: grid.z selects among (B0,C0),(B1,C1),(B2,C2)
template<bool BIAS, bool GELU, bool ACCUM, bool QKV3>
__global__ __launch_bounds__(256,2) void sgemm_k(
    const float* __restrict__ A,
    const float* __restrict__ B0, const float* __restrict__ B1, const float* __restrict__ B2,
    const float* __restrict__ bias,
    float* __restrict__ C0, float* __restrict__ C1, float* __restrict__ C2,
    int M, int N, int K)
{
    const float* B = B0;
    float* C = C0;
    if (QKV3){
        if (blockIdx.z==1){ B=B1; C=C1; }
        else if (blockIdx.z==2){ B=B2; C=C2; }
    }
    __shared__ float As[2][8][128];
    __shared__ float Bs[2][8][128];
    const int tid = threadIdx.x;
    const int bx = blockIdx.x, by = blockIdx.y;
    const int arow = tid >> 1, acol = (tid & 1) << 2;
    const int brow = tid >> 5, bcol = (tid & 31) << 2;
    const float* Ap = A + (size_t)(by*128 + arow)*K + acol;
    const float* Bp = B + (size_t)brow*N + bx*128 + bcol;
    const int tx = tid & 15, ty = tid >> 4;
    float acc[8][8];
    #pragma unroll
    for (int i=0;i<8;i++)
        #pragma unroll
        for (int j=0;j<8;j++) acc[i][j]=0.f;

    // prologue: load tile 0 into buf 0
    float4 av = *(const float4*)Ap; Ap += 8;
    float4 bv = *(const float4*)Bp; Bp += (size_t)8*N;
    As[0][acol+0][arow]=av.x; As[0][acol+1][arow]=av.y;
    As[0][acol+2][arow]=av.z; As[0][acol+3][arow]=av.w;
    *(float4*)&Bs[0][brow][bcol] = bv;
    __syncthreads();

    int buf = 0;
    for (int k0=8;k0<K;k0+=8){
        // issue next tile loads early
        av = *(const float4*)Ap; Ap += 8;
        bv = *(const float4*)Bp; Bp += (size_t)8*N;
        // compute on current buffer
        #pragma unroll
        for (int kk=0;kk<8;kk++){
            float a[8], b[8];
            *(float4*)(a)   = *(const float4*)&As[buf][kk][ty*8];
            *(float4*)(a+4) = *(const float4*)&As[buf][kk][ty*8+4];
            *(float4*)(b)   = *(const float4*)&Bs[buf][kk][tx*8];
            *(float4*)(b+4) = *(const float4*)&Bs[buf][kk][tx*8+4];
            #pragma unroll
            for (int i=0;i<8;i++)
                #pragma unroll
                for (int j=0;j<8;j++)
                    acc[i][j] = fmaf(a[i], b[j], acc[i][j]);
        }
        // stage into the other buffer
        const int nb = buf ^ 1;
        As[nb][acol+0][arow]=av.x; As[nb][acol+1][arow]=av.y;
        As[nb][acol+2][arow]=av.z; As[nb][acol+3][arow]=av.w;
        *(float4*)&Bs[nb][brow][bcol] = bv;
        __syncthreads();
        buf = nb;
    }
    // epilogue compute on last buffer
    #pragma unroll
    for (int kk=0;kk<8;kk++){
        float a[8], b[8];
        *(float4*)(a)   = *(const float4*)&As[buf][kk][ty*8];
        *(float4*)(a+4) = *(const float4*)&As[buf][kk][ty*8+4];
        *(float4*)(b)   = *(const float4*)&Bs[buf][kk][tx*8];
        *(float4*)(b+4) = *(const float4*)&Bs[buf][kk][tx*8+4];
        #pragma unroll
        for (int i=0;i<8;i++)
            #pragma unroll
            for (int j=0;j<8;j++)
                acc[i][j] = fmaf(a[i], b[j], acc[i][j]);
    }

    const int cbase = bx*128 + tx*8;
    #pragma unroll
    for (int i=0;i<8;i++){
        float* Cp = C + (size_t)(by*128 + ty*8 + i)*N + cbase;
        #pragma unroll
        for (int jj=0;jj<8;jj+=4){
            float4 v4 = make_float4(acc[i][jj],acc[i][jj+1],acc[i][jj+2],acc[i][jj+3]);
            if (BIAS){
                float4 b4 = *(const float4*)(bias + cbase + jj);
                v4.x+=b4.x; v4.y+=b4.y; v4.z+=b4.z; v4.w+=b4.w;
            }
            if (GELU){
                v4.x=gelu_f(v4.x); v4.y=gelu_f(v4.y); v4.z=gelu_f(v4.z); v4.w=gelu_f(v4.w);
            }
            if (ACCUM){
                float4 o4 = *(float4*)(Cp+jj);
                v4.x+=o4.x; v4.y+=o4.y; v4.z+=o4.z; v4.w+=o4.w;
            }
            *(float4*)(Cp+jj) = v4;
        }
    }
}

// ---------------- fused edge attention (single pass, no segment max) --------
__device__ __forceinline__ void fma4(float4& a, float s, const float4& w){
    a.x = fmaf(s,w.x,a.x); a.y = fmaf(s,w.y,a.y);
    a.z = fmaf(s,w.z,a.z); a.w = fmaf(s,w.w,a.w);
}
__device__ __forceinline__ void red_add4(float* p, float4 v){
    asm volatile("red.global.add.v4.f32 [%0], {%1,%2,%3,%4};"
                 :: "l"(p), "f"(v.x), "f"(v.y), "f"(v.z), "f"(v.w) : "memory");
}

// lane owns channels [8*lane, 8*lane+8); head = lane>>2 (4 lanes per head)
__global__ void edge_attn_k(const int* __restrict__ src, const int* __restrict__ dst,
                            const float* __restrict__ ea, const float* __restrict__ Wep,
                            const float* __restrict__ q,  const float* __restrict__ kmat,
                            const float* __restrict__ vmat,
                            float* __restrict__ msg, float* __restrict__ den, int E)
{
    extern __shared__ float4 sWe[];                    // 64 x 256 floats = 64KB
    const float4* We4 = (const float4*)Wep;
    for (int i=threadIdx.x; i<EDIM*HDIM/4; i+=blockDim.x) sWe[i]=We4[i];
    __syncthreads();
    const int lane = threadIdx.x & 31;
    const int wid  = blockIdx.x*(blockDim.x>>5) + (threadIdx.x>>5);
    const int nw   = gridDim.x*(blockDim.x>>5);
    for (int base = wid*EB; base < E; base += nw*EB){
        const int ne = min(EB, E-base);
        float a0[EB], a1[EB]; int si[EB], di[EB];
        #pragma unroll
        for (int t=0;t<EB;t++){
            int ee = (t<ne)? base+t : base;
            a0[t]=ea[ee*EDIM+lane]; a1[t]=ea[ee*EDIM+32+lane];
            si[t]=src[ee]; di[t]=dst[ee];
        }
        float4 e0[EB], e1[EB];
        #pragma unroll
        for (int t=0;t<EB;t++){ e0[t]=make_float4(0,0,0,0); e1[t]=make_float4(0,0,0,0); }

        #pragma unroll 4
        for (int kk=0;kk<32;kk++){
            float4 w0=sWe[kk*64 + (lane<<1)];
            float4 w1=sWe[kk*64 + (lane<<1)+1];
            #pragma unroll
            for (int t=0;t<EB;t++){
                float av=__shfl_sync(0xffffffffu, a0[t], kk);
                fma4(e0[t],av,w0); fma4(e1[t],av,w1);
            }
        }
        #pragma unroll 4
        for (int kk=0;kk<32;kk++){
            float4 w0=sWe[(kk+32)*64 + (lane<<1)];
            float4 w1=sWe[(kk+32)*64 + (lane<<1)+1];
            #pragma unroll
            for (int t=0;t<EB;t++){
                float av=__shfl_sync(0xffffffffu, a1[t], kk);
                fma4(e0[t],av,w0); fma4(e1[t],av,w1);
            }
        }
        #pragma unroll
        for (int t=0;t<EB;t++){
            const float4* qr=(const float4*)(q    + (size_t)di[t]*HDIM) + (lane<<1);
            const float4* kr=(const float4*)(kmat + (size_t)si[t]*HDIM) + (lane<<1);
            float4 q0=qr[0], q1=qr[1], k0=kr[0], k1=kr[1];
            float s = q0.x*(k0.x+e0[t].x)+q0.y*(k0.y+e0[t].y)
                    + q0.z*(k0.z+e0[t].z)+q0.w*(k0.w+e0[t].w)
                    + q1.x*(k1.x+e1[t].x)+q1.y*(k1.y+e1[t].y)
                    + q1.z*(k1.z+e1[t].z)+q1.w*(k1.w+e1[t].w);
            s += __shfl_xor_sync(0xffffffffu, s, 1);
            s += __shfl_xor_sync(0xffffffffu, s, 2);
            float ex = expf(s * 0.17677669529663687f);   // DH^-0.5
            const float4* vr=(const float4*)(vmat + (size_t)si[t]*HDIM) + (lane<<1);
            float4 v0=vr[0], v1=vr[1];
            float4 m0=make_float4(ex*(v0.x+e0[t].x), ex*(v0.y+e0[t].y),
                                  ex*(v0.z+e0[t].z), ex*(v0.w+e0[t].w));
            float4 m1=make_float4(ex*(v1.x+e1[t].x), ex*(v1.y+e1[t].y),
                                  ex*(v1.z+e1[t].z), ex*(v1.w+e1[t].w));
            if (t<ne){
                if ((lane&3)==0) atomicAdd(den + (size_t)di[t]*8 + (lane>>2), ex);
                float* mp = msg + (size_t)di[t]*HDIM + lane*8;
                red_add4(mp,   m0);
                red_add4(mp+4, m1);
            }
        }
    }
}

__global__ void norm_msg_k(float* __restrict__ msg, const float* __restrict__ den, int total){
    int i=blockIdx.x*blockDim.x+threadIdx.x;
    if (i<total){
        int node=i>>8, h=(i>>5)&7;
        msg[i] = msg[i] / (den[node*8+h] + 1e-9f);
    }
}

// x = LN(x + a), one warp per row
__global__ void add_ln_k(float* __restrict__ x, const float* __restrict__ a, int M){
    int row  = blockIdx.x*(blockDim.x>>5) + (threadIdx.x>>5);
    int lane = threadIdx.x & 31;
    if (row>=M) return;
    float vals[8]; float s=0.f;
    float* xp = x + (size_t)row*HDIM;
    const float* ap = a + (size_t)row*HDIM;
    #pragma unroll
    for (int i=0;i<8;i++){ vals[i]=xp[lane+32*i]+ap[lane+32*i]; s+=vals[i]; }
    #pragma unroll
    for (int o=16;o;o>>=1) s += __shfl_xor_sync(0xffffffffu,s,o);
    float mean=s*(1.f/HDIM);
    float vsum=0.f;
    #pragma unroll
    for (int i=0;i<8;i++){ float d=vals[i]-mean; vsum+=d*d; }
    #pragma unroll
    for (int o=16;o;o>>=1) vsum += __shfl_xor_sync(0xffffffffu,vsum,o);
    float inv = rsqrtf(vsum*(1.f/HDIM)+1e-5f);
    #pragma unroll
    for (int i=0;i<8;i++) xp[lane+32*i]=(vals[i]-mean)*inv;
}

__global__ void head2_k(const float* __restrict__ g, const float* __restrict__ w2,
                        const float* __restrict__ b2, float* __restrict__ out, int M){
    int r=blockIdx.x*blockDim.x+threadIdx.x;
    if (r>=M) return;
    float acc[7];
    #pragma unroll
    for (int j=0;j<7;j++) acc[j]=b2[j];
    const float* gr = g + (size_t)r*HDIM;
    for (int k2=0;k2<HDIM;k2++){
        float gv=gr[k2];
        #pragma unroll
        for (int j=0;j<7;j++) acc[j]=fmaf(gv, w2[k2*7+j], acc[j]);
    }
    float* op = out + (size_t)r*7;
    #pragma unroll
    for (int j=0;j<7;j++) op[j]=acc[j];
}

// ---------------------------- host side -------------------------------------
enum {L_XL,L_XR,L_EALL,L_EARR,L_EALR,L_EARL,L_EILL,L_EIRR,L_EILR,L_EIRL,
      L_WQ,L_WK,L_WV,L_WE,L_WO,L_F1,L_FB1,L_F2,L_FB2,L_HW1,L_HB1,L_HW2,L_HB2,L_ACT};

static const int lsize[24] = {
    4718592,4718592,18874368,18874368,4194304,4194304,
    589824,589824,131072,131072,
    524288,524288,524288,131072,524288,
    524288,2048,524288,1024,65536,256,1792,7,1};

static const int ord_dict[24]={L_XL,L_XR,L_EALL,L_EARR,L_EALR,L_EARL,
    L_EILL,L_EIRR,L_EILR,L_EIRL,
    L_WQ,L_WK,L_WV,L_WE,L_WO,L_F1,L_FB1,L_F2,L_FB2,L_HW1,L_HB1,L_HW2,L_HB2,L_ACT};
static const int ord_sig[24]={L_XL,L_XR,L_EALL,L_EARR,L_EALR,L_EARL,
    L_WQ,L_WK,L_WV,L_WE,L_WO,L_F1,L_FB1,L_F2,L_FB2,L_HW1,L_HB1,L_HW2,L_HB2,
    L_EILL,L_EIRR,L_EILR,L_EIRL,L_ACT};
static const int ord_alpha[24]={L_WE,L_WK,L_WO,L_WQ,L_WV,L_ACT,L_XL,L_XR,
    L_EALL,L_EALR,L_EARL,L_EARR,L_EILL,L_EILR,L_EIRL,L_EIRR,
    L_FB1,L_FB2,L_F1,L_F2,L_HB1,L_HB2,L_HW1,L_HW2};

static void run_attn(const float* xq, const float* xk,
                     const int* ei, const float* ea, int E,
                     const float* Wq, const float* Wk, const float* Wv,
                     const float* Wep, const float* Wo,
                     float* agg, bool accum,
                     float* q, float* k, float* v, float* msg, float* den)
{
    dim3 tb(256);
    dim3 g3(HDIM/128, N_NODES/128, 3);
    dim3 g2(HDIM/128, N_NODES/128);
    // q = xq@Wq ; k = xk@Wk ; v = xk@Wv   (one fused launch, grid.z picks)
    sgemm_k<false,false,false,true><<<g3,tb>>>(xq, Wq, Wk, Wv, nullptr, q, k, v,
                                               N_NODES, HDIM, HDIM);
    // NOTE: z=1,2 use A=xq; when xk!=xq we must run k/v separately.
    if (xk != xq){
        dim3 g2b(HDIM/128, N_NODES/128, 2);
        // overwrite k,v with correct A
        sgemm_k<false,false,false,true><<<g2b,tb>>>(xk, Wk, Wv, Wv, nullptr, k, v, v,
                                                    N_NODES, HDIM, HDIM);
    }
    cudaMemsetAsync(msg,0,(size_t)N_NODES*HDIM*sizeof(float),0);
    cudaMemsetAsync(den,0,(size_t)N_NODES*8*sizeof(float),0);
    edge_attn_k<<<592,256,65536,0>>>(ei, ei+E, ea, Wep, q,k,v,msg,den,E);
    int tot=N_NODES*HDIM;
    norm_msg_k<<<(tot+255)/256,256>>>(msg,den,tot);
    if (accum) sgemm_k<false,false,true ,false><<<g2,tb>>>(msg,Wo,nullptr,nullptr,nullptr,agg,nullptr,nullptr,N_NODES,HDIM,HDIM);
    else       sgemm_k<false,false,false,false><<<g2,tb>>>(msg,Wo,nullptr,nullptr,nullptr,agg,nullptr,nullptr,N_NODES,HDIM,HDIM);
}

extern "C" void kernel_launch(void* const* d_in, const int* in_sizes, int n_in,
                              void* d_out, int out_size)
{
    // ---- resolve input ordering by size fingerprint ----
    const int* cands[3] = {ord_dict, ord_sig, ord_alpha};
    const int* ord = nullptr;
    int lim = n_in < 24 ? n_in : 24;
    for (int c=0;c<3 && !ord;c++){
        bool ok = true;
        for (int i=0;i<lim;i++)
            if (in_sizes[i] != lsize[cands[c][i]]) { ok=false; break; }
        if (ok) ord = cands[c];
    }
    if (!ord) ord = ord_dict;
    const void* p[24] = {};
    for (int i=0;i<lim;i++) p[ord[i]] = d_in[i];

    const float* xl_in = (const float*)p[L_XL];
    const float* xr_in = (const float*)p[L_XR];
    const float* ea_ll = (const float*)p[L_EALL];
    const float* ea_rr = (const float*)p[L_EARR];
    const float* ea_lr = (const float*)p[L_EALR];
    const float* ea_rl = (const float*)p[L_EARL];
    const int*   ei_ll = (const int*)  p[L_EILL];
    const int*   ei_rr = (const int*)  p[L_EIRR];
    const int*   ei_lr = (const int*)  p[L_EILR];
    const int*   ei_rl = (const int*)  p[L_EIRL];
    const float* WQ = (const float*)p[L_WQ];
    const float* WK = (const float*)p[L_WK];
    const float* WV = (const float*)p[L_WV];
    const float* WE = (const float*)p[L_WE];
    const float* WO = (const float*)p[L_WO];
    const float* F1 = (const float*)p[L_F1];
    const float* FB1= (const float*)p[L_FB1];
    const float* F2 = (const float*)p[L_F2];
    const float* FB2= (const float*)p[L_FB2];
    const float* HW1= (const float*)p[L_HW1];
    const float* HB1= (const float*)p[L_HB1];
    const float* HW2= (const float*)p[L_HW2];
    const float* HB2= (const float*)p[L_HB2];

    float *xl,*xr,*q,*k,*v,*msg,*den,*aggl,*aggr,*hid;
    cudaGetSymbolAddress((void**)&xl,  g_xl);
    cudaGetSymbolAddress((void**)&xr,  g_xr);
    cudaGetSymbolAddress((void**)&q,   g_q);
    cudaGetSymbolAddress((void**)&k,   g_k);
    cudaGetSymbolAddress((void**)&v,   g_v);
    cudaGetSymbolAddress((void**)&msg, g_msg);
    cudaGetSymbolAddress((void**)&den, g_den);
    cudaGetSymbolAddress((void**)&aggl,g_aggl);
    cudaGetSymbolAddress((void**)&aggr,g_aggr);
    cudaGetSymbolAddress((void**)&hid, g_hid);

    cudaFuncSetAttribute(edge_attn_k, cudaFuncAttributeMaxDynamicSharedMemorySize, 65536);

    cudaMemcpyAsync(xl, xl_in, (size_t)N_NODES*HDIM*sizeof(float), cudaMemcpyDeviceToDevice, 0);
    cudaMemcpyAsync(xr, xr_in, (size_t)N_NODES*HDIM*sizeof(float), cudaMemcpyDeviceToDevice, 0);

    dim3 tb(256);
    for (int l=0;l<NLAY;l++){
        const size_t wOff = (size_t)HDIM*HDIM;
        const size_t eOff = (size_t)EDIM*HDIM;
        #define WQT(t) (WQ + ((size_t)l*4+(t))*wOff)
        #define WKT(t) (WK + ((size_t)l*4+(t))*wOff)
        #define WVT(t) (WV + ((size_t)l*4+(t))*wOff)
        #define WET(t) (WE + ((size_t)l*4+(t))*eOff)
        #define WOT(t) (WO + ((size_t)l*4+(t))*wOff)

        // agg_l = attn(xl,xl,ll,t0) + attn(xl,xr,rl,t3)
        run_attn(xl, xl, ei_ll, ea_ll, E_BIG, WQT(0),WKT(0),WVT(0),WET(0),WOT(0),
                 aggl, false, q,k,v,msg,den);
        run_attn(xl, xr, ei_rl, ea_rl, E_SML, WQT(3),WKT(3),WVT(3),WET(3),WOT(3),
                 aggl, true,  q,k,v,msg,den);
        // agg_r = attn(xr,xr,rr,t1) + attn(xr,xl,lr,t2)
        run_attn(xr, xr, ei_rr, ea_rr, E_BIG, WQT(1),WKT(1),WVT(1),WET(1),WOT(1),
                 aggr, false, q,k,v,msg,den);
        run_attn(xr, xl, ei_lr, ea_lr, E_SML, WQT(2),WKT(2),WVT(2),WET(2),WOT(2),
                 aggr, true,  q,k,v,msg,den);

        add_ln_k<<<N_NODES/8,256>>>(xl, aggl, N_NODES);
        add_ln_k<<<N_NODES/8,256>>>(xr, aggr, N_NODES);

        // FFN left (s=0), right (s=1)
        const float* f1l = F1 + ((size_t)l*2+0)*HDIM*FDIM;
        const float* b1l = FB1+ ((size_t)l*2+0)*FDIM;
        const float* f2l = F2 + ((size_t)l*2+0)*FDIM*HDIM;
        const float* b2l = FB2+ ((size_t)l*2+0)*HDIM;
        sgemm_k<true,true ,false,false><<<dim3(FDIM/128,N_NODES/128),tb>>>(
            xl,f1l,nullptr,nullptr,b1l,hid,nullptr,nullptr,N_NODES,FDIM,HDIM);
        sgemm_k<true,false,false,false><<<dim3(HDIM/128,N_NODES/128),tb>>>(
            hid,f2l,nullptr,nullptr,b2l,aggl,nullptr,nullptr,N_NODES,HDIM,FDIM);
        add_ln_k<<<N_NODES/8,256>>>(xl, aggl, N_NODES);

        const float* f1r = F1 + ((size_t)l*2+1)*HDIM*FDIM;
        const float* b1r = FB1+ ((size_t)l*2+1)*FDIM;
        const float* f2r = F2 + ((size_t)l*2+1)*FDIM*HDIM;
        const float* b2r = FB2+ ((size_t)l*2+1)*HDIM;
        sgemm_k<true,true ,false,false><<<dim3(FDIM/128,N_NODES/128),tb>>>(
            xr,f1r,nullptr,nullptr,b1r,hid,nullptr,nullptr,N_NODES,FDIM,HDIM);
        sgemm_k<true,false,false,false><<<dim3(HDIM/128,N_NODES/128),tb>>>(
            hid,f2r,nullptr,nullptr,b2r,aggr,nullptr,nullptr,N_NODES,HDIM,FDIM);
        add_ln_k<<<N_NODES/8,256>>>(xr, aggr, N_NODES);
        #undef WQT
        #undef WKT
        #undef WVT
        #undef WET
        #undef WOT
    }

    // heads on rows [start, N)
    int rows  = out_size / 14;          // 16384
    int start = N_NODES - rows;         // 2048
    float* out = (float*)d_out;

    sgemm_k<true,true,false,false><<<dim3(HDIM/128, rows/128),tb>>>(
        xl + (size_t)start*HDIM, HW1, nullptr, nullptr, HB1, hid, nullptr, nullptr,
        rows, HDIM, HDIM);
    head2_k<<<(rows+255)/256,256>>>(hid, HW2, HB2, out, rows);

    sgemm_k<true,true,false,false><<<dim3(HDIM/128, rows/128),tb>>>(
        xr + (size_t)start*HDIM, HW1, nullptr, nullptr, HB1, hid, nullptr, nullptr,
        rows, HDIM, HDIM);
    head2_k<<<(rows+255)/256,256>>>(hid, HW2, HB2, out + (size_t)rows*7, rows);
}

// round 5
// speedup vs baseline: 1.4704x; 1.4704x over previous
#include <cuda_runtime.h>
#include <cuda_bf16.h>
#include <math.h>

#define N_NODES 18432
#define HDIM    256
#define EDIM    64
#define FDIM    512
#define NLAY    2
#define E_BIG   294912
#define E_SML   65536
#define EB      4

// ---------------- scratch (device globals; no allocs allowed) ----------------
__device__ float g_xl [N_NODES*HDIM];
__device__ float g_xr [N_NODES*HDIM];
__device__ float g_q  [N_NODES*HDIM];
__device__ float g_k  [N_NODES*HDIM];
__device__ float g_v  [N_NODES*HDIM];
__device__ float g_msg[N_NODES*HDIM];
__device__ float g_den[N_NODES*8];
__device__ float g_aggl[N_NODES*HDIM];
__device__ float g_aggr[N_NODES*HDIM];
__device__ float g_hid[N_NODES*FDIM];

__device__ __forceinline__ float gelu_f(float x){
    return 0.5f*x*(1.0f + tanhf(0.7978845608028654f*(x + 0.044715f*x*x*x)));
}
__device__ __forceinline__ unsigned tf32_of(float x){
    unsigned r;
    asm("cvt.rna.tf32.f32 %0, %1;" : "=r"(r) : "f"(x));
    return r;
}
__device__ __forceinline__ void mma_tf32(float c[4], const unsigned a[4],
                                         unsigned b0, unsigned b1){
    asm volatile("mma.sync.aligned.m16n8k8.row.col.f32.tf32.tf32.f32 "
        "{%0,%1,%2,%3}, {%4,%5,%6,%7}, {%8,%9}, {%0,%1,%2,%3};"
        : "+f"(c[0]), "+f"(c[1]), "+f"(c[2]), "+f"(c[3])
        : "r"(a[0]), "r"(a[1]), "r"(a[2]), "r"(a[3]), "r"(b0), "r"(b1));
}

// ---------------- TF32 tensor-core GEMM --------------------------------------
// C[M,N] = A[M,K] @ B[K,N] (row-major). 128x128 block tile, BK=16,
// double-buffered smem, 256 threads = 8 warps of 32x64.
// QKV3: grid.z selects among (B0,C0),(B1,C1),(B2,C2).
template<bool BIAS, bool GELU, bool ACCUM, bool QKV3>
__global__ __launch_bounds__(256,2) void tgemm_k(
    const float* __restrict__ A,
    const float* __restrict__ B0, const float* __restrict__ B1, const float* __restrict__ B2,
    const float* __restrict__ bias,
    float* __restrict__ C0, float* __restrict__ C1, float* __restrict__ C2,
    int M, int N, int K)
{
    const float* B = B0;
    float* C = C0;
    if (QKV3){
        if (blockIdx.z==1){ B=B1; C=C1; }
        else if (blockIdx.z==2){ B=B2; C=C2; }
    }
    __shared__ unsigned As[2][16][136];   // [k][m], padded: bank-conflict-free frags
    __shared__ unsigned Bs[2][16][136];   // [k][n]

    const int tid  = threadIdx.x;
    const int bx = blockIdx.x, by = blockIdx.y;
    const int warp = tid >> 5, lane = tid & 31;
    const int wm = warp >> 1, wn = warp & 1;          // 4x2 warp grid
    const int g  = lane >> 2, c = lane & 3;

    // global load mapping
    const int arow  = tid & 127;                      // A row within tile
    const int ahalf = (tid >> 7) * 8;                 // k-cols [ahalf, ahalf+8)
    const int bk    = tid >> 4;                       // B k-row (0..15)
    const int bn    = (tid & 15) * 8;                 // B n-cols [bn, bn+8)
    const float* Ap = A + (size_t)(by*128 + arow)*K + ahalf;
    const float* Bp = B + (size_t)bk*N + bx*128 + bn;

    float acc[2][8][4];
    #pragma unroll
    for (int mi=0;mi<2;mi++)
        #pragma unroll
        for (int ni=0;ni<8;ni++)
            #pragma unroll
            for (int r=0;r<4;r++) acc[mi][ni][r]=0.f;

    float4 av0,av1,bv0,bv1;
    // prologue: load tile 0
    av0 = *(const float4*)Ap; av1 = *(const float4*)(Ap+4);
    bv0 = *(const float4*)Bp; bv1 = *(const float4*)(Bp+4);
    As[0][ahalf+0][arow]=tf32_of(av0.x); As[0][ahalf+1][arow]=tf32_of(av0.y);
    As[0][ahalf+2][arow]=tf32_of(av0.z); As[0][ahalf+3][arow]=tf32_of(av0.w);
    As[0][ahalf+4][arow]=tf32_of(av1.x); As[0][ahalf+5][arow]=tf32_of(av1.y);
    As[0][ahalf+6][arow]=tf32_of(av1.z); As[0][ahalf+7][arow]=tf32_of(av1.w);
    {
        unsigned* br = &Bs[0][bk][bn];
        br[0]=tf32_of(bv0.x); br[1]=tf32_of(bv0.y); br[2]=tf32_of(bv0.z); br[3]=tf32_of(bv0.w);
        br[4]=tf32_of(bv1.x); br[5]=tf32_of(bv1.y); br[6]=tf32_of(bv1.z); br[7]=tf32_of(bv1.w);
    }
    __syncthreads();

    int buf = 0;
    for (int k0=16;k0<=K;k0+=16){
        if (k0 < K){
            const float* Apn = Ap + k0;
            const float* Bpn = Bp + (size_t)k0*N;
            av0 = *(const float4*)Apn; av1 = *(const float4*)(Apn+4);
            bv0 = *(const float4*)Bpn; bv1 = *(const float4*)(Bpn+4);
        }
        // compute current buffer: two k8 steps
        #pragma unroll
        for (int ks=0;ks<16;ks+=8){
            unsigned af[2][4];
            #pragma unroll
            for (int mi=0;mi<2;mi++){
                const int mr = wm*32 + mi*16;
                af[mi][0] = As[buf][ks+c  ][mr+g];
                af[mi][1] = As[buf][ks+c  ][mr+g+8];
                af[mi][2] = As[buf][ks+c+4][mr+g];
                af[mi][3] = As[buf][ks+c+4][mr+g+8];
            }
            #pragma unroll
            for (int ni=0;ni<8;ni++){
                const int nc = wn*64 + ni*8 + g;
                unsigned b0 = Bs[buf][ks+c  ][nc];
                unsigned b1 = Bs[buf][ks+c+4][nc];
                mma_tf32(acc[0][ni], af[0], b0, b1);
                mma_tf32(acc[1][ni], af[1], b0, b1);
            }
        }
        if (k0 < K){
            const int nb = buf ^ 1;
            As[nb][ahalf+0][arow]=tf32_of(av0.x); As[nb][ahalf+1][arow]=tf32_of(av0.y);
            As[nb][ahalf+2][arow]=tf32_of(av0.z); As[nb][ahalf+3][arow]=tf32_of(av0.w);
            As[nb][ahalf+4][arow]=tf32_of(av1.x); As[nb][ahalf+5][arow]=tf32_of(av1.y);
            As[nb][ahalf+6][arow]=tf32_of(av1.z); As[nb][ahalf+7][arow]=tf32_of(av1.w);
            unsigned* br = &Bs[nb][bk][bn];
            br[0]=tf32_of(bv0.x); br[1]=tf32_of(bv0.y); br[2]=tf32_of(bv0.z); br[3]=tf32_of(bv0.w);
            br[4]=tf32_of(bv1.x); br[5]=tf32_of(bv1.y); br[6]=tf32_of(bv1.z); br[7]=tf32_of(bv1.w);
            __syncthreads();
            buf = nb;
        }
    }

    // epilogue: c0=(g,2c) c1=(g,2c+1) c2=(g+8,2c) c3=(g+8,2c+1)
    #pragma unroll
    for (int mi=0;mi<2;mi++){
        const int r0 = by*128 + wm*32 + mi*16 + g;
        #pragma unroll
        for (int ni=0;ni<8;ni++){
            const int col = bx*128 + wn*64 + ni*8 + 2*c;
            float2 vA = make_float2(acc[mi][ni][0], acc[mi][ni][1]);
            float2 vB = make_float2(acc[mi][ni][2], acc[mi][ni][3]);
            if (BIAS){
                float2 b2 = *(const float2*)(bias + col);
                vA.x+=b2.x; vA.y+=b2.y; vB.x+=b2.x; vB.y+=b2.y;
            }
            if (GELU){
                vA.x=gelu_f(vA.x); vA.y=gelu_f(vA.y);
                vB.x=gelu_f(vB.x); vB.y=gelu_f(vB.y);
            }
            float* p0 = C + (size_t)r0*N + col;
            float* p1 = C + (size_t)(r0+8)*N + col;
            if (ACCUM){
                float2 o0=*(float2*)p0, o1=*(float2*)p1;
                vA.x+=o0.x; vA.y+=o0.y; vB.x+=o1.x; vB.y+=o1.y;
            }
            *(float2*)p0 = vA;
            *(float2*)p1 = vB;
        }
    }
}

// ---------------- fused edge attention (single pass, no segment max) --------
__device__ __forceinline__ void fma4(float4& a, float s, const float4& w){
    a.x = fmaf(s,w.x,a.x); a.y = fmaf(s,w.y,a.y);
    a.z = fmaf(s,w.z,a.z); a.w = fmaf(s,w.w,a.w);
}
__device__ __forceinline__ void red_add4(float* p, float4 v){
    asm volatile("red.global.add.v4.f32 [%0], {%1,%2,%3,%4};"
                 :: "l"(p), "f"(v.x), "f"(v.y), "f"(v.z), "f"(v.w) : "memory");
}

// lane owns channels [8*lane, 8*lane+8); head = lane>>2 (4 lanes per head)
__global__ void edge_attn_k(const int* __restrict__ src, const int* __restrict__ dst,
                            const float* __restrict__ ea, const float* __restrict__ Wep,
                            const float* __restrict__ q,  const float* __restrict__ kmat,
                            const float* __restrict__ vmat,
                            float* __restrict__ msg, float* __restrict__ den, int E)
{
    extern __shared__ float4 sWe[];                    // 64 x 256 floats = 64KB
    const float4* We4 = (const float4*)Wep;
    for (int i=threadIdx.x; i<EDIM*HDIM/4; i+=blockDim.x) sWe[i]=We4[i];
    __syncthreads();
    const int lane = threadIdx.x & 31;
    const int wid  = blockIdx.x*(blockDim.x>>5) + (threadIdx.x>>5);
    const int nw   = gridDim.x*(blockDim.x>>5);
    for (int base = wid*EB; base < E; base += nw*EB){
        const int ne = min(EB, E-base);
        float a0[EB], a1[EB]; int si[EB], di[EB];
        #pragma unroll
        for (int t=0;t<EB;t++){
            int ee = (t<ne)? base+t : base;
            a0[t]=ea[ee*EDIM+lane]; a1[t]=ea[ee*EDIM+32+lane];
            si[t]=src[ee]; di[t]=dst[ee];
        }
        float4 e0[EB], e1[EB];
        #pragma unroll
        for (int t=0;t<EB;t++){ e0[t]=make_float4(0,0,0,0); e1[t]=make_float4(0,0,0,0); }

        #pragma unroll 4
        for (int kk=0;kk<32;kk++){
            float4 w0=sWe[kk*64 + (lane<<1)];
            float4 w1=sWe[kk*64 + (lane<<1)+1];
            #pragma unroll
            for (int t=0;t<EB;t++){
                float av=__shfl_sync(0xffffffffu, a0[t], kk);
                fma4(e0[t],av,w0); fma4(e1[t],av,w1);
            }
        }
        #pragma unroll 4
        for (int kk=0;kk<32;kk++){
            float4 w0=sWe[(kk+32)*64 + (lane<<1)];
            float4 w1=sWe[(kk+32)*64 + (lane<<1)+1];
            #pragma unroll
            for (int t=0;t<EB;t++){
                float av=__shfl_sync(0xffffffffu, a1[t], kk);
                fma4(e0[t],av,w0); fma4(e1[t],av,w1);
            }
        }
        #pragma unroll
        for (int t=0;t<EB;t++){
            const float4* qr=(const float4*)(q    + (size_t)di[t]*HDIM) + (lane<<1);
            const float4* kr=(const float4*)(kmat + (size_t)si[t]*HDIM) + (lane<<1);
            float4 q0=qr[0], q1=qr[1], k0=kr[0], k1=kr[1];
            float s = q0.x*(k0.x+e0[t].x)+q0.y*(k0.y+e0[t].y)
                    + q0.z*(k0.z+e0[t].z)+q0.w*(k0.w+e0[t].w)
                    + q1.x*(k1.x+e1[t].x)+q1.y*(k1.y+e1[t].y)
                    + q1.z*(k1.z+e1[t].z)+q1.w*(k1.w+e1[t].w);
            s += __shfl_xor_sync(0xffffffffu, s, 1);
            s += __shfl_xor_sync(0xffffffffu, s, 2);
            float ex = expf(s * 0.17677669529663687f);   // DH^-0.5
            const float4* vr=(const float4*)(vmat + (size_t)si[t]*HDIM) + (lane<<1);
            float4 v0=vr[0], v1=vr[1];
            float4 m0=make_float4(ex*(v0.x+e0[t].x), ex*(v0.y+e0[t].y),
                                  ex*(v0.z+e0[t].z), ex*(v0.w+e0[t].w));
            float4 m1=make_float4(ex*(v1.x+e1[t].x), ex*(v1.y+e1[t].y),
                                  ex*(v1.z+e1[t].z), ex*(v1.w+e1[t].w));
            if (t<ne){
                if ((lane&3)==0) atomicAdd(den + (size_t)di[t]*8 + (lane>>2), ex);
                float* mp = msg + (size_t)di[t]*HDIM + lane*8;
                red_add4(mp,   m0);
                red_add4(mp+4, m1);
            }
        }
    }
}

__global__ void norm_msg_k(float* __restrict__ msg, const float* __restrict__ den, int total){
    int i=blockIdx.x*blockDim.x+threadIdx.x;
    if (i<total){
        int node=i>>8, h=(i>>5)&7;
        msg[i] = msg[i] / (den[node*8+h] + 1e-9f);
    }
}

// x = LN(x + a), one warp per row
__global__ void add_ln_k(float* __restrict__ x, const float* __restrict__ a, int M){
    int row  = blockIdx.x*(blockDim.x>>5) + (threadIdx.x>>5);
    int lane = threadIdx.x & 31;
    if (row>=M) return;
    float vals[8]; float s=0.f;
    float* xp = x + (size_t)row*HDIM;
    const float* ap = a + (size_t)row*HDIM;
    #pragma unroll
    for (int i=0;i<8;i++){ vals[i]=xp[lane+32*i]+ap[lane+32*i]; s+=vals[i]; }
    #pragma unroll
    for (int o=16;o;o>>=1) s += __shfl_xor_sync(0xffffffffu,s,o);
    float mean=s*(1.f/HDIM);
    float vsum=0.f;
    #pragma unroll
    for (int i=0;i<8;i++){ float d=vals[i]-mean; vsum+=d*d; }
    #pragma unroll
    for (int o=16;o;o>>=1) vsum += __shfl_xor_sync(0xffffffffu,vsum,o);
    float inv = rsqrtf(vsum*(1.f/HDIM)+1e-5f);
    #pragma unroll
    for (int i=0;i<8;i++) xp[lane+32*i]=(vals[i]-mean)*inv;
}

__global__ void head2_k(const float* __restrict__ g, const float* __restrict__ w2,
                        const float* __restrict__ b2, float* __restrict__ out, int M){
    int r=blockIdx.x*blockDim.x+threadIdx.x;
    if (r>=M) return;
    float acc[7];
    #pragma unroll
    for (int j=0;j<7;j++) acc[j]=b2[j];
    const float* gr = g + (size_t)r*HDIM;
    for (int k2=0;k2<HDIM;k2++){
        float gv=gr[k2];
        #pragma unroll
        for (int j=0;j<7;j++) acc[j]=fmaf(gv, w2[k2*7+j], acc[j]);
    }
    float* op = out + (size_t)r*7;
    #pragma unroll
    for (int j=0;j<7;j++) op[j]=acc[j];
}

// ---------------------------- host side -------------------------------------
enum {L_XL,L_XR,L_EALL,L_EARR,L_EALR,L_EARL,L_EILL,L_EIRR,L_EILR,L_EIRL,
      L_WQ,L_WK,L_WV,L_WE,L_WO,L_F1,L_FB1,L_F2,L_FB2,L_HW1,L_HB1,L_HW2,L_HB2,L_ACT};

static const int lsize[24] = {
    4718592,4718592,18874368,18874368,4194304,4194304,
    589824,589824,131072,131072,
    524288,524288,524288,131072,524288,
    524288,2048,524288,1024,65536,256,1792,7,1};

static const int ord_dict[24]={L_XL,L_XR,L_EALL,L_EARR,L_EALR,L_EARL,
    L_EILL,L_EIRR,L_EILR,L_EIRL,
    L_WQ,L_WK,L_WV,L_WE,L_WO,L_F1,L_FB1,L_F2,L_FB2,L_HW1,L_HB1,L_HW2,L_HB2,L_ACT};
static const int ord_sig[24]={L_XL,L_XR,L_EALL,L_EARR,L_EALR,L_EARL,
    L_WQ,L_WK,L_WV,L_WE,L_WO,L_F1,L_FB1,L_F2,L_FB2,L_HW1,L_HB1,L_HW2,L_HB2,
    L_EILL,L_EIRR,L_EILR,L_EIRL,L_ACT};
static const int ord_alpha[24]={L_WE,L_WK,L_WO,L_WQ,L_WV,L_ACT,L_XL,L_XR,
    L_EALL,L_EALR,L_EARL,L_EARR,L_EILL,L_EILR,L_EIRL,L_EIRR,
    L_FB1,L_FB2,L_F1,L_F2,L_HB1,L_HB2,L_HW1,L_HW2};

static void run_attn(const float* xq, const float* xk,
                     const int* ei, const float* ea, int E,
                     const float* Wq, const float* Wk, const float* Wv,
                     const float* Wep, const float* Wo,
                     float* agg, bool accum,
                     float* q, float* k, float* v, float* msg, float* den)
{
    dim3 tb(256);
    dim3 g2(HDIM/128, N_NODES/128);
    if (xq == xk){
        dim3 g3(HDIM/128, N_NODES/128, 3);
        tgemm_k<false,false,false,true><<<g3,tb>>>(xq, Wq, Wk, Wv, nullptr, q, k, v,
                                                   N_NODES, HDIM, HDIM);
    } else {
        tgemm_k<false,false,false,false><<<g2,tb>>>(xq, Wq, nullptr, nullptr, nullptr,
                                                    q, nullptr, nullptr, N_NODES, HDIM, HDIM);
        dim3 g2b(HDIM/128, N_NODES/128, 2);
        tgemm_k<false,false,false,true><<<g2b,tb>>>(xk, Wk, Wv, nullptr, nullptr,
                                                    k, v, nullptr, N_NODES, HDIM, HDIM);
    }
    cudaMemsetAsync(msg,0,(size_t)N_NODES*HDIM*sizeof(float),0);
    cudaMemsetAsync(den,0,(size_t)N_NODES*8*sizeof(float),0);
    edge_attn_k<<<592,256,65536,0>>>(ei, ei+E, ea, Wep, q,k,v,msg,den,E);
    int tot=N_NODES*HDIM;
    norm_msg_k<<<(tot+255)/256,256>>>(msg,den,tot);
    if (accum) tgemm_k<false,false,true ,false><<<g2,tb>>>(msg,Wo,nullptr,nullptr,nullptr,agg,nullptr,nullptr,N_NODES,HDIM,HDIM);
    else       tgemm_k<false,false,false,false><<<g2,tb>>>(msg,Wo,nullptr,nullptr,nullptr,agg,nullptr,nullptr,N_NODES,HDIM,HDIM);
}

extern "C" void kernel_launch(void* const* d_in, const int* in_sizes, int n_in,
                              void* d_out, int out_size)
{
    // ---- resolve input ordering by size fingerprint ----
    const int* cands[3] = {ord_dict, ord_sig, ord_alpha};
    const int* ord = nullptr;
    int lim = n_in < 24 ? n_in : 24;
    for (int c=0;c<3 && !ord;c++){
        bool ok = true;
        for (int i=0;i<lim;i++)
            if (in_sizes[i] != lsize[cands[c][i]]) { ok=false; break; }
        if (ok) ord = cands[c];
    }
    if (!ord) ord = ord_dict;
    const void* p[24] = {};
    for (int i=0;i<lim;i++) p[ord[i]] = d_in[i];

    const float* xl_in = (const float*)p[L_XL];
    const float* xr_in = (const float*)p[L_XR];
    const float* ea_ll = (const float*)p[L_EALL];
    const float* ea_rr = (const float*)p[L_EARR];
    const float* ea_lr = (const float*)p[L_EALR];
    const float* ea_rl = (const float*)p[L_EARL];
    const int*   ei_ll = (const int*)  p[L_EILL];
    const int*   ei_rr = (const int*)  p[L_EIRR];
    const int*   ei_lr = (const int*)  p[L_EILR];
    const int*   ei_rl = (const int*)  p[L_EIRL];
    const float* WQ = (const float*)p[L_WQ];
    const float* WK = (const float*)p[L_WK];
    const float* WV = (const float*)p[L_WV];
    const float* WE = (const float*)p[L_WE];
    const float* WO = (const float*)p[L_WO];
    const float* F1 = (const float*)p[L_F1];
    const float* FB1= (const float*)p[L_FB1];
    const float* F2 = (const float*)p[L_F2];
    const float* FB2= (const float*)p[L_FB2];
    const float* HW1= (const float*)p[L_HW1];
    const float* HB1= (const float*)p[L_HB1];
    const float* HW2= (const float*)p[L_HW2];
    const float* HB2= (const float*)p[L_HB2];

    float *xl,*xr,*q,*k,*v,*msg,*den,*aggl,*aggr,*hid;
    cudaGetSymbolAddress((void**)&xl,  g_xl);
    cudaGetSymbolAddress((void**)&xr,  g_xr);
    cudaGetSymbolAddress((void**)&q,   g_q);
    cudaGetSymbolAddress((void**)&k,   g_k);
    cudaGetSymbolAddress((void**)&v,   g_v);
    cudaGetSymbolAddress((void**)&msg, g_msg);
    cudaGetSymbolAddress((void**)&den, g_den);
    cudaGetSymbolAddress((void**)&aggl,g_aggl);
    cudaGetSymbolAddress((void**)&aggr,g_aggr);
    cudaGetSymbolAddress((void**)&hid, g_hid);

    cudaFuncSetAttribute(edge_attn_k, cudaFuncAttributeMaxDynamicSharedMemorySize, 65536);

    cudaMemcpyAsync(xl, xl_in, (size_t)N_NODES*HDIM*sizeof(float), cudaMemcpyDeviceToDevice, 0);
    cudaMemcpyAsync(xr, xr_in, (size_t)N_NODES*HDIM*sizeof(float), cudaMemcpyDeviceToDevice, 0);

    dim3 tb(256);
    for (int l=0;l<NLAY;l++){
        const size_t wOff = (size_t)HDIM*HDIM;
        const size_t eOff = (size_t)EDIM*HDIM;
        #define WQT(t) (WQ + ((size_t)l*4+(t))*wOff)
        #define WKT(t) (WK + ((size_t)l*4+(t))*wOff)
        #define WVT(t) (WV + ((size_t)l*4+(t))*wOff)
        #define WET(t) (WE + ((size_t)l*4+(t))*eOff)
        #define WOT(t) (WO + ((size_t)l*4+(t))*wOff)

        // agg_l = attn(xl,xl,ll,t0) + attn(xl,xr,rl,t3)
        run_attn(xl, xl, ei_ll, ea_ll, E_BIG, WQT(0),WKT(0),WVT(0),WET(0),WOT(0),
                 aggl, false, q,k,v,msg,den);
        run_attn(xl, xr, ei_rl, ea_rl, E_SML, WQT(3),WKT(3),WVT(3),WET(3),WOT(3),
                 aggl, true,  q,k,v,msg,den);
        // agg_r = attn(xr,xr,rr,t1) + attn(xr,xl,lr,t2)
        run_attn(xr, xr, ei_rr, ea_rr, E_BIG, WQT(1),WKT(1),WVT(1),WET(1),WOT(1),
                 aggr, false, q,k,v,msg,den);
        run_attn(xr, xl, ei_lr, ea_lr, E_SML, WQT(2),WKT(2),WVT(2),WET(2),WOT(2),
                 aggr, true,  q,k,v,msg,den);

        add_ln_k<<<N_NODES/8,256>>>(xl, aggl, N_NODES);
        add_ln_k<<<N_NODES/8,256>>>(xr, aggr, N_NODES);

        // FFN left (s=0), right (s=1)
        const float* f1l = F1 + ((size_t)l*2+0)*HDIM*FDIM;
        const float* b1l = FB1+ ((size_t)l*2+0)*FDIM;
        const float* f2l = F2 + ((size_t)l*2+0)*FDIM*HDIM;
        const float* b2l = FB2+ ((size_t)l*2+0)*HDIM;
        tgemm_k<true,true ,false,false><<<dim3(FDIM/128,N_NODES/128),tb>>>(
            xl,f1l,nullptr,nullptr,b1l,hid,nullptr,nullptr,N_NODES,FDIM,HDIM);
        tgemm_k<true,false,false,false><<<dim3(HDIM/128,N_NODES/128),tb>>>(
            hid,f2l,nullptr,nullptr,b2l,aggl,nullptr,nullptr,N_NODES,HDIM,FDIM);
        add_ln_k<<<N_NODES/8,256>>>(xl, aggl, N_NODES);

        const float* f1r = F1 + ((size_t)l*2+1)*HDIM*FDIM;
        const float* b1r = FB1+ ((size_t)l*2+1)*FDIM;
        const float* f2r = F2 + ((size_t)l*2+1)*FDIM*HDIM;
        const float* b2r = FB2+ ((size_t)l*2+1)*HDIM;
        tgemm_k<true,true ,false,false><<<dim3(FDIM/128,N_NODES/128),tb>>>(
            xr,f1r,nullptr,nullptr,b1r,hid,nullptr,nullptr,N_NODES,FDIM,HDIM);
        tgemm_k<true,false,false,false><<<dim3(HDIM/128,N_NODES/128),tb>>>(
            hid,f2r,nullptr,nullptr,b2r,aggr,nullptr,nullptr,N_NODES,HDIM,FDIM);
        add_ln_k<<<N_NODES/8,256>>>(xr, aggr, N_NODES);
        #undef WQT
        #undef WKT
        #undef WVT
        #undef WET
        #undef WOT
    }

    // heads on rows [start, N)
    int rows  = out_size / 14;          // 16384
    int start = N_NODES - rows;         // 2048
    float* out = (float*)d_out;

    tgemm_k<true,true,false,false><<<dim3(HDIM/128, rows/128),tb>>>(
        xl + (size_t)start*HDIM, HW1, nullptr, nullptr, HB1, hid, nullptr, nullptr,
        rows, HDIM, HDIM);
    head2_k<<<(rows+255)/256,256>>>(hid, HW2, HB2, out, rows);

    tgemm_k<true,true,false,false><<<dim3(HDIM/128, rows/128),tb>>>(
        xr + (size_t)start*HDIM, HW1, nullptr, nullptr, HB1, hid, nullptr, nullptr,
        rows, HDIM, HDIM);
    head2_k<<<(rows+255)/256,256>>>(hid, HW2, HB2, out + (size_t)rows*7, rows);
}

// round 7
// speedup vs baseline: 1.5591x; 1.0603x over previous
#include <cuda_runtime.h>
#include <cuda_bf16.h>
#include <math.h>

#define N_NODES 18432
#define HDIM    256
#define EDIM    64
#define FDIM    512
#define NLAY    2
#define E_BIG   294912
#define E_SML   65536
#define EB      4

// ---------------- scratch (device globals; no allocs allowed) ----------------
__device__ float g_xl [N_NODES*HDIM];
__device__ float g_xr [N_NODES*HDIM];
__device__ float g_qkv[12][N_NODES*HDIM];     // 12 projection buffers
__device__ float g_msg[2*N_NODES*512];        // msgL | msgR, row stride 512
__device__ float g_den[2*N_NODES*16];         // denL | denR, row stride 16
__device__ float g_agg[2][N_NODES*HDIM];
__device__ float g_hid[2][N_NODES*FDIM];

__device__ __forceinline__ float gelu_f(float x){
    return 0.5f*x*(1.0f + tanhf(0.7978845608028654f*(x + 0.044715f*x*x*x)));
}
__device__ __forceinline__ unsigned tf32_of(float x){
    unsigned r;
    asm("cvt.rna.tf32.f32 %0, %1;" : "=r"(r) : "f"(x));
    return r;
}
__device__ __forceinline__ void mma_tf32(float c[4], const unsigned a[4],
                                         unsigned b0, unsigned b1){
    asm volatile("mma.sync.aligned.m16n8k8.row.col.f32.tf32.tf32.f32 "
        "{%0,%1,%2,%3}, {%4,%5,%6,%7}, {%8,%9}, {%0,%1,%2,%3};"
        : "+f"(c[0]), "+f"(c[1]), "+f"(c[2]), "+f"(c[3])
        : "r"(a[0]), "r"(a[1]), "r"(a[2]), "r"(a[3]), "r"(b0), "r"(b1));
}

// ---------------- batched TF32 tensor-core GEMM ------------------------------
// Per-z GEMM: C[z] = op(A[z] @ [B[z];B2[z]]) . 128x128 tile, BK=16, K=KT.
// NORM: A element (m,k) scaled by 1/(den[z][m*16 + k/32]+1e-9) before cvt.
// SPLITB: B rows [0,256) from B[z], rows [256,KT) from B2[z].
struct GP {
    const float* A[6];
    const float* B[6];
    const float* B2[6];
    const float* bias[6];
    const float* den[6];
    float*       C[6];
    int N;
};

template<int KT, bool BIAS, bool GELU, bool NORM, bool SPLITB>
__global__ __launch_bounds__(256,2) void tgemm_k(GP p)
{
    const int z = blockIdx.z;
    const float* __restrict__ A = p.A[z];
    const float* __restrict__ B = p.B[z];
    float* __restrict__ C = p.C[z];
    const int N = p.N;

    __shared__ unsigned As[2][16][136];
    __shared__ unsigned Bs[2][16][136];

    const int tid = threadIdx.x;
    const int bx = blockIdx.x, by = blockIdx.y;
    const int warp = tid >> 5, lane = tid & 31;
    const int wm = warp >> 1, wn = warp & 1;
    const int g  = lane >> 2, c = lane & 3;

    const int arow  = tid & 127;
    const int ahalf = (tid >> 7) * 8;
    const int bk    = tid >> 4;
    const int bn    = (tid & 15) * 8;
    const int grow  = by*128 + arow;
    const float* Abase = A + (size_t)grow*KT + ahalf;
    const float* Bp    = B + (size_t)bk*N + bx*128 + bn;
    const float* dptr  = NORM ? (p.den[z] + (size_t)grow*16) : nullptr;

    float acc[2][8][4];
    #pragma unroll
    for (int mi=0;mi<2;mi++)
        #pragma unroll
        for (int ni=0;ni<8;ni++)
            #pragma unroll
            for (int r=0;r<4;r++) acc[mi][ni][r]=0.f;

    float4 av0,av1,bv0,bv1;
    // prologue: tile 0
    av0 = *(const float4*)(Abase);   av1 = *(const float4*)(Abase+4);
    bv0 = *(const float4*)(Bp);      bv1 = *(const float4*)(Bp+4);
    Bp += (size_t)16*N;
    if (NORM){
        float rd = 1.0f/(dptr[ahalf>>5] + 1e-9f);
        av0.x*=rd; av0.y*=rd; av0.z*=rd; av0.w*=rd;
        av1.x*=rd; av1.y*=rd; av1.z*=rd; av1.w*=rd;
    }
    As[0][ahalf+0][arow]=tf32_of(av0.x); As[0][ahalf+1][arow]=tf32_of(av0.y);
    As[0][ahalf+2][arow]=tf32_of(av0.z); As[0][ahalf+3][arow]=tf32_of(av0.w);
    As[0][ahalf+4][arow]=tf32_of(av1.x); As[0][ahalf+5][arow]=tf32_of(av1.y);
    As[0][ahalf+6][arow]=tf32_of(av1.z); As[0][ahalf+7][arow]=tf32_of(av1.w);
    {
        unsigned* br = &Bs[0][bk][bn];
        br[0]=tf32_of(bv0.x); br[1]=tf32_of(bv0.y); br[2]=tf32_of(bv0.z); br[3]=tf32_of(bv0.w);
        br[4]=tf32_of(bv1.x); br[5]=tf32_of(bv1.y); br[6]=tf32_of(bv1.z); br[7]=tf32_of(bv1.w);
    }
    __syncthreads();

    int buf = 0;
    #pragma unroll 4
    for (int k0=16;k0<=KT;k0+=16){
        const bool has_next = (k0 < KT);
        if (has_next){
            if (SPLITB && k0 == 256)
                Bp = p.B2[z] + (size_t)bk*N + bx*128 + bn;
            av0 = *(const float4*)(Abase + k0);   av1 = *(const float4*)(Abase + k0 + 4);
            bv0 = *(const float4*)(Bp);           bv1 = *(const float4*)(Bp + 4);
            Bp += (size_t)16*N;
            if (NORM){
                float rd = 1.0f/(dptr[(k0+ahalf)>>5] + 1e-9f);
                av0.x*=rd; av0.y*=rd; av0.z*=rd; av0.w*=rd;
                av1.x*=rd; av1.y*=rd; av1.z*=rd; av1.w*=rd;
            }
        }
        #pragma unroll
        for (int ks=0;ks<16;ks+=8){
            unsigned af[2][4];
            #pragma unroll
            for (int mi=0;mi<2;mi++){
                const int mr = wm*32 + mi*16;
                af[mi][0] = As[buf][ks+c  ][mr+g];
                af[mi][1] = As[buf][ks+c  ][mr+g+8];
                af[mi][2] = As[buf][ks+c+4][mr+g];
                af[mi][3] = As[buf][ks+c+4][mr+g+8];
            }
            #pragma unroll
            for (int ni=0;ni<8;ni++){
                const int nc = wn*64 + ni*8 + g;
                unsigned b0 = Bs[buf][ks+c  ][nc];
                unsigned b1 = Bs[buf][ks+c+4][nc];
                mma_tf32(acc[0][ni], af[0], b0, b1);
                mma_tf32(acc[1][ni], af[1], b0, b1);
            }
        }
        if (has_next){
            const int nb = buf ^ 1;
            As[nb][ahalf+0][arow]=tf32_of(av0.x); As[nb][ahalf+1][arow]=tf32_of(av0.y);
            As[nb][ahalf+2][arow]=tf32_of(av0.z); As[nb][ahalf+3][arow]=tf32_of(av0.w);
            As[nb][ahalf+4][arow]=tf32_of(av1.x); As[nb][ahalf+5][arow]=tf32_of(av1.y);
            As[nb][ahalf+6][arow]=tf32_of(av1.z); As[nb][ahalf+7][arow]=tf32_of(av1.w);
            unsigned* br = &Bs[nb][bk][bn];
            br[0]=tf32_of(bv0.x); br[1]=tf32_of(bv0.y); br[2]=tf32_of(bv0.z); br[3]=tf32_of(bv0.w);
            br[4]=tf32_of(bv1.x); br[5]=tf32_of(bv1.y); br[6]=tf32_of(bv1.z); br[7]=tf32_of(bv1.w);
            __syncthreads();
            buf = nb;
        }
    }

    const float* bias = BIAS ? p.bias[z] : nullptr;
    #pragma unroll
    for (int mi=0;mi<2;mi++){
        const int r0 = by*128 + wm*32 + mi*16 + g;
        #pragma unroll
        for (int ni=0;ni<8;ni++){
            const int col = bx*128 + wn*64 + ni*8 + 2*c;
            float2 vA = make_float2(acc[mi][ni][0], acc[mi][ni][1]);
            float2 vB = make_float2(acc[mi][ni][2], acc[mi][ni][3]);
            if (BIAS){
                float2 b2 = *(const float2*)(bias + col);
                vA.x+=b2.x; vA.y+=b2.y; vB.x+=b2.x; vB.y+=b2.y;
            }
            if (GELU){
                vA.x=gelu_f(vA.x); vA.y=gelu_f(vA.y);
                vB.x=gelu_f(vB.x); vB.y=gelu_f(vB.y);
            }
            *(float2*)(C + (size_t)r0*N + col)     = vA;
            *(float2*)(C + (size_t)(r0+8)*N + col) = vB;
        }
    }
}

// ---------------- fused edge attention (batched z=4) -------------------------
__device__ __forceinline__ void fma4(float4& a, float s, const float4& w){
    a.x = fmaf(s,w.x,a.x); a.y = fmaf(s,w.y,a.y);
    a.z = fmaf(s,w.z,a.z); a.w = fmaf(s,w.w,a.w);
}
__device__ __forceinline__ void red_add4(float* p, float4 v){
    asm volatile("red.global.add.v4.f32 [%0], {%1,%2,%3,%4};"
                 :: "l"(p), "f"(v.x), "f"(v.y), "f"(v.z), "f"(v.w) : "memory");
}

struct EP {
    const int* src; const int* dst;
    const float* ea; const float* We;
    const float* q; const float* k; const float* v;
    float* msg;   // pre-offset: + side*N*512 + colbase
    float* den;   // pre-offset: + side*N*16  + headbase
    int E;
};
struct EP4 { EP e[4]; };

// lane owns channels [8*lane, 8*lane+8); head = lane>>2 (4 lanes per head)
// msg row stride 512, den row stride 16.
__global__ void edge_attn_k(EP4 P)
{
    const EP ep = P.e[blockIdx.z];
    extern __shared__ float4 sWe[];                    // 64 x 256 floats = 64KB
    const float4* We4 = (const float4*)ep.We;
    for (int i=threadIdx.x; i<EDIM*HDIM/4; i+=blockDim.x) sWe[i]=We4[i];
    __syncthreads();
    const int lane = threadIdx.x & 31;
    const int wid  = blockIdx.x*(blockDim.x>>5) + (threadIdx.x>>5);
    const int nw   = gridDim.x*(blockDim.x>>5);
    const int E = ep.E;
    const int* __restrict__ src = ep.src;
    const int* __restrict__ dst = ep.dst;
    const float* __restrict__ ea = ep.ea;
    const float* __restrict__ q = ep.q;
    const float* __restrict__ kmat = ep.k;
    const float* __restrict__ vmat = ep.v;
    float* __restrict__ msg = ep.msg;
    float* __restrict__ den = ep.den;

    for (int base = wid*EB; base < E; base += nw*EB){
        const int ne = min(EB, E-base);
        float a0[EB], a1[EB]; int si[EB], di[EB];
        #pragma unroll
        for (int t=0;t<EB;t++){
            int ee = (t<ne)? base+t : base;
            a0[t]=ea[ee*EDIM+lane]; a1[t]=ea[ee*EDIM+32+lane];
            si[t]=src[ee]; di[t]=dst[ee];
        }
        float4 e0[EB], e1[EB];
        #pragma unroll
        for (int t=0;t<EB;t++){ e0[t]=make_float4(0,0,0,0); e1[t]=make_float4(0,0,0,0); }

        #pragma unroll 4
        for (int kk=0;kk<32;kk++){
            float4 w0=sWe[kk*64 + (lane<<1)];
            float4 w1=sWe[kk*64 + (lane<<1)+1];
            #pragma unroll
            for (int t=0;t<EB;t++){
                float av=__shfl_sync(0xffffffffu, a0[t], kk);
                fma4(e0[t],av,w0); fma4(e1[t],av,w1);
            }
        }
        #pragma unroll 4
        for (int kk=0;kk<32;kk++){
            float4 w0=sWe[(kk+32)*64 + (lane<<1)];
            float4 w1=sWe[(kk+32)*64 + (lane<<1)+1];
            #pragma unroll
            for (int t=0;t<EB;t++){
                float av=__shfl_sync(0xffffffffu, a1[t], kk);
                fma4(e0[t],av,w0); fma4(e1[t],av,w1);
            }
        }
        #pragma unroll
        for (int t=0;t<EB;t++){
            const float4* qr=(const float4*)(q    + (size_t)di[t]*HDIM) + (lane<<1);
            const float4* kr=(const float4*)(kmat + (size_t)si[t]*HDIM) + (lane<<1);
            float4 q0=qr[0], q1=qr[1], k0=kr[0], k1=kr[1];
            float s = q0.x*(k0.x+e0[t].x)+q0.y*(k0.y+e0[t].y)
                    + q0.z*(k0.z+e0[t].z)+q0.w*(k0.w+e0[t].w)
                    + q1.x*(k1.x+e1[t].x)+q1.y*(k1.y+e1[t].y)
                    + q1.z*(k1.z+e1[t].z)+q1.w*(k1.w+e1[t].w);
            s += __shfl_xor_sync(0xffffffffu, s, 1);
            s += __shfl_xor_sync(0xffffffffu, s, 2);
            float ex = expf(s * 0.17677669529663687f);   // DH^-0.5
            const float4* vr=(const float4*)(vmat + (size_t)si[t]*HDIM) + (lane<<1);
            float4 v0=vr[0], v1=vr[1];
            float4 m0=make_float4(ex*(v0.x+e0[t].x), ex*(v0.y+e0[t].y),
                                  ex*(v0.z+e0[t].z), ex*(v0.w+e0[t].w));
            float4 m1=make_float4(ex*(v1.x+e1[t].x), ex*(v1.y+e1[t].y),
                                  ex*(v1.z+e1[t].z), ex*(v1.w+e1[t].w));
            if (t<ne){
                if ((lane&3)==0) atomicAdd(den + (size_t)di[t]*16 + (lane>>2), ex);
                float* mp = msg + (size_t)di[t]*512 + lane*8;
                red_add4(mp,   m0);
                red_add4(mp+4, m1);
            }
        }
    }
}

// x = LN(x + a) for both sides; grid.y selects side; one warp per row
__global__ void add_ln_k(float* __restrict__ x0, const float* __restrict__ a0,
                         float* __restrict__ x1, const float* __restrict__ a1, int M){
    int row  = blockIdx.x*(blockDim.x>>5) + (threadIdx.x>>5);
    int lane = threadIdx.x & 31;
    if (row>=M) return;
    float* x = blockIdx.y ? x1 : x0;
    const float* a = blockIdx.y ? a1 : a0;
    float vals[8]; float s=0.f;
    float* xp = x + (size_t)row*HDIM;
    const float* ap = a + (size_t)row*HDIM;
    #pragma unroll
    for (int i=0;i<8;i++){ vals[i]=xp[lane+32*i]+ap[lane+32*i]; s+=vals[i]; }
    #pragma unroll
    for (int o=16;o;o>>=1) s += __shfl_xor_sync(0xffffffffu,s,o);
    float mean=s*(1.f/HDIM);
    float vsum=0.f;
    #pragma unroll
    for (int i=0;i<8;i++){ float d=vals[i]-mean; vsum+=d*d; }
    #pragma unroll
    for (int o=16;o;o>>=1) vsum += __shfl_xor_sync(0xffffffffu,vsum,o);
    float inv = rsqrtf(vsum*(1.f/HDIM)+1e-5f);
    #pragma unroll
    for (int i=0;i<8;i++) xp[lane+32*i]=(vals[i]-mean)*inv;
}

__global__ void head2_k(const float* __restrict__ g0, const float* __restrict__ g1,
                        const float* __restrict__ w2, const float* __restrict__ b2,
                        float* __restrict__ out, int rows){
    int r=blockIdx.x*blockDim.x+threadIdx.x;
    if (r>=2*rows) return;
    const float* gr = (r < rows) ? (g0 + (size_t)r*HDIM)
                                 : (g1 + (size_t)(r-rows)*HDIM);
    float acc[7];
    #pragma unroll
    for (int j=0;j<7;j++) acc[j]=b2[j];
    for (int k2=0;k2<HDIM;k2++){
        float gv=gr[k2];
        #pragma unroll
        for (int j=0;j<7;j++) acc[j]=fmaf(gv, w2[k2*7+j], acc[j]);
    }
    float* op = out + (size_t)r*7;
    #pragma unroll
    for (int j=0;j<7;j++) op[j]=acc[j];
}

// ---------------------------- host side -------------------------------------
enum {L_XL,L_XR,L_EALL,L_EARR,L_EALR,L_EARL,L_EILL,L_EIRR,L_EILR,L_EIRL,
      L_WQ,L_WK,L_WV,L_WE,L_WO,L_F1,L_FB1,L_F2,L_FB2,L_HW1,L_HB1,L_HW2,L_HB2,L_ACT};

static const int lsize[24] = {
    4718592,4718592,18874368,18874368,4194304,4194304,
    589824,589824,131072,131072,
    524288,524288,524288,131072,524288,
    524288,2048,524288,1024,65536,256,1792,7,1};

static const int ord_dict[24]={L_XL,L_XR,L_EALL,L_EARR,L_EALR,L_EARL,
    L_EILL,L_EIRR,L_EILR,L_EIRL,
    L_WQ,L_WK,L_WV,L_WE,L_WO,L_F1,L_FB1,L_F2,L_FB2,L_HW1,L_HB1,L_HW2,L_HB2,L_ACT};
static const int ord_sig[24]={L_XL,L_XR,L_EALL,L_EARR,L_EALR,L_EARL,
    L_WQ,L_WK,L_WV,L_WE,L_WO,L_F1,L_FB1,L_F2,L_FB2,L_HW1,L_HB1,L_HW2,L_HB2,
    L_EILL,L_EIRR,L_EILR,L_EIRL,L_ACT};
static const int ord_alpha[24]={L_WE,L_WK,L_WO,L_WQ,L_WV,L_ACT,L_XL,L_XR,
    L_EALL,L_EALR,L_EARL,L_EARR,L_EILL,L_EILR,L_EIRL,L_EIRR,
    L_FB1,L_FB2,L_F1,L_F2,L_HB1,L_HB2,L_HW1,L_HW2};

extern "C" void kernel_launch(void* const* d_in, const int* in_sizes, int n_in,
                              void* d_out, int out_size)
{
    // ---- resolve input ordering by size fingerprint ----
    const int* cands[3] = {ord_dict, ord_sig, ord_alpha};
    const int* ord = nullptr;
    int lim = n_in < 24 ? n_in : 24;
    for (int c=0;c<3 && !ord;c++){
        bool ok = true;
        for (int i=0;i<lim;i++)
            if (in_sizes[i] != lsize[cands[c][i]]) { ok=false; break; }
        if (ok) ord = cands[c];
    }
    if (!ord) ord = ord_dict;
    const void* p[24] = {};
    for (int i=0;i<lim;i++) p[ord[i]] = d_in[i];

    const float* xl_in = (const float*)p[L_XL];
    const float* xr_in = (const float*)p[L_XR];
    const float* ea_ll = (const float*)p[L_EALL];
    const float* ea_rr = (const float*)p[L_EARR];
    const float* ea_lr = (const float*)p[L_EALR];
    const float* ea_rl = (const float*)p[L_EARL];
    const int*   ei_ll = (const int*)  p[L_EILL];
    const int*   ei_rr = (const int*)  p[L_EIRR];
    const int*   ei_lr = (const int*)  p[L_EILR];
    const int*   ei_rl = (const int*)  p[L_EIRL];
    const float* WQ = (const float*)p[L_WQ];
    const float* WK = (const float*)p[L_WK];
    const float* WV = (const float*)p[L_WV];
    const float* WE = (const float*)p[L_WE];
    const float* WO = (const float*)p[L_WO];
    const float* F1 = (const float*)p[L_F1];
    const float* FB1= (const float*)p[L_FB1];
    const float* F2 = (const float*)p[L_F2];
    const float* FB2= (const float*)p[L_FB2];
    const float* HW1= (const float*)p[L_HW1];
    const float* HB1= (const float*)p[L_HB1];
    const float* HW2= (const float*)p[L_HW2];
    const float* HB2= (const float*)p[L_HB2];

    float *xl,*xr,*qkv,*msg,*den,*agg,*hid;
    cudaGetSymbolAddress((void**)&xl,  g_xl);
    cudaGetSymbolAddress((void**)&xr,  g_xr);
    cudaGetSymbolAddress((void**)&qkv, g_qkv);
    cudaGetSymbolAddress((void**)&msg, g_msg);
    cudaGetSymbolAddress((void**)&den, g_den);
    cudaGetSymbolAddress((void**)&agg, g_agg);
    cudaGetSymbolAddress((void**)&hid, g_hid);

    float* msgL = msg;                 float* msgR = msg + (size_t)N_NODES*512;
    float* denL = den;                 float* denR = den + (size_t)N_NODES*16;
    float* aggl = agg;                 float* aggr = agg + (size_t)N_NODES*HDIM;
    float* hidL = hid;                 float* hidR = hid + (size_t)N_NODES*FDIM;
    #define QB(i) (qkv + (size_t)(i)*N_NODES*HDIM)

    cudaFuncSetAttribute(edge_attn_k, cudaFuncAttributeMaxDynamicSharedMemorySize, 65536);

    cudaMemcpyAsync(xl, xl_in, (size_t)N_NODES*HDIM*sizeof(float), cudaMemcpyDeviceToDevice, 0);
    cudaMemcpyAsync(xr, xr_in, (size_t)N_NODES*HDIM*sizeof(float), cudaMemcpyDeviceToDevice, 0);

    const size_t wOff = (size_t)HDIM*HDIM;
    const size_t eOff = (size_t)EDIM*HDIM;
    dim3 tb(256);

    for (int l=0;l<NLAY;l++){
        #define WQT(t) (WQ + ((size_t)l*4+(t))*wOff)
        #define WKT(t) (WK + ((size_t)l*4+(t))*wOff)
        #define WVT(t) (WV + ((size_t)l*4+(t))*wOff)
        #define WET(t) (WE + ((size_t)l*4+(t))*eOff)
        #define WOT(t) (WO + ((size_t)l*4+(t))*wOff)

        // ---- all 12 q/k/v projections, 2 launches (z=6) ----
        // xl batch: Q_ll,K_ll,V_ll,Q_rl,K_lr,V_lr -> buffers 0..5
        {
            GP pa{}; pa.N = HDIM;
            const float* Bs6[6] = {WQT(0),WKT(0),WVT(0),WQT(3),WKT(2),WVT(2)};
            for (int z2=0;z2<6;z2++){ pa.A[z2]=xl; pa.B[z2]=Bs6[z2]; pa.C[z2]=QB(z2); }
            tgemm_k<256,false,false,false,false><<<dim3(2,144,6),tb>>>(pa);
        }
        // xr batch: Q_rr,K_rr,V_rr,Q_lr,K_rl,V_rl -> buffers 6..11
        {
            GP pa{}; pa.N = HDIM;
            const float* Bs6[6] = {WQT(1),WKT(1),WVT(1),WQT(2),WKT(3),WVT(3)};
            for (int z2=0;z2<6;z2++){ pa.A[z2]=xr; pa.B[z2]=Bs6[z2]; pa.C[z2]=QB(6+z2); }
            tgemm_k<256,false,false,false,false><<<dim3(2,144,6),tb>>>(pa);
        }

        cudaMemsetAsync(msg, 0, (size_t)2*N_NODES*512*sizeof(float), 0);
        cudaMemsetAsync(den, 0, (size_t)2*N_NODES*16*sizeof(float), 0);

        // ---- 4 edge-attention calls in one launch (z=4) ----
        {
            EP4 P;
            // ll: dst side L, cols 0-255
            P.e[0] = {ei_ll, ei_ll+E_BIG, ea_ll, WET(0), QB(0), QB(1),  QB(2),
                      msgL,       denL,     E_BIG};
            // rl: dst side L, cols 256-511
            P.e[1] = {ei_rl, ei_rl+E_SML, ea_rl, WET(3), QB(3), QB(10), QB(11),
                      msgL+256,   denL+8,   E_SML};
            // rr: dst side R, cols 0-255
            P.e[2] = {ei_rr, ei_rr+E_BIG, ea_rr, WET(1), QB(6), QB(7),  QB(8),
                      msgR,       denR,     E_BIG};
            // lr: dst side R, cols 256-511
            P.e[3] = {ei_lr, ei_lr+E_SML, ea_lr, WET(2), QB(9), QB(4),  QB(5),
                      msgR+256,   denR+8,   E_SML};
            edge_attn_k<<<dim3(592,1,4),tb,65536>>>(P);
        }

        // ---- output projection: agg = norm(msg) @ [Wo;Wo'] (K=512), z=2 ----
        {
            GP pw{}; pw.N = HDIM;
            pw.A[0]=msgL; pw.B[0]=WOT(0); pw.B2[0]=WOT(3); pw.den[0]=denL; pw.C[0]=aggl;
            pw.A[1]=msgR; pw.B[1]=WOT(1); pw.B2[1]=WOT(2); pw.den[1]=denR; pw.C[1]=aggr;
            tgemm_k<512,false,false,true,true><<<dim3(2,144,2),tb>>>(pw);
        }

        add_ln_k<<<dim3(N_NODES/8,2),tb>>>(xl,aggl,xr,aggr,N_NODES);

        // ---- FFN (both sides batched) ----
        {
            GP pf{}; pf.N = FDIM;
            pf.A[0]=xl; pf.B[0]=F1+((size_t)l*2+0)*HDIM*FDIM; pf.bias[0]=FB1+((size_t)l*2+0)*FDIM; pf.C[0]=hidL;
            pf.A[1]=xr; pf.B[1]=F1+((size_t)l*2+1)*HDIM*FDIM; pf.bias[1]=FB1+((size_t)l*2+1)*FDIM; pf.C[1]=hidR;
            tgemm_k<256,true,true,false,false><<<dim3(4,144,2),tb>>>(pf);
        }
        {
            GP pf{}; pf.N = HDIM;
            pf.A[0]=hidL; pf.B[0]=F2+((size_t)l*2+0)*FDIM*HDIM; pf.bias[0]=FB2+((size_t)l*2+0)*HDIM; pf.C[0]=aggl;
            pf.A[1]=hidR; pf.B[1]=F2+((size_t)l*2+1)*FDIM*HDIM; pf.bias[1]=FB2+((size_t)l*2+1)*HDIM; pf.C[1]=aggr;
            tgemm_k<512,true,false,false,false><<<dim3(2,144,2),tb>>>(pf);
        }
        add_ln_k<<<dim3(N_NODES/8,2),tb>>>(xl,aggl,xr,aggr,N_NODES);

        #undef WQT
        #undef WKT
        #undef WVT
        #undef WET
        #undef WOT
    }

    // ---- heads on rows [start, N), both sides batched ----
    int rows  = out_size / 14;          // 16384
    int start = N_NODES - rows;         // 2048
    float* out = (float*)d_out;
    {
        GP ph{}; ph.N = HDIM;
        ph.A[0]=xl + (size_t)start*HDIM; ph.B[0]=HW1; ph.bias[0]=HB1; ph.C[0]=hidL;
        ph.A[1]=xr + (size_t)start*HDIM; ph.B[1]=HW1; ph.bias[1]=HB1; ph.C[1]=hidR;
        tgemm_k<256,true,true,false,false><<<dim3(2,rows/128,2),tb>>>(ph);
    }
    head2_k<<<(2*rows+255)/256,tb>>>(hidL,hidR,HW2,HB2,out,rows);
}